// round 2
// baseline (speedup 1.0000x reference)
#include <cuda_runtime.h>
#include <cuda_fp16.h>
#include <cstdint>

#define B_  4
#define LQ  512
#define LK  512
#define DQ  256
#define DC  256
#define H_  128

typedef unsigned long long ull;

// Scratch (__device__ globals: allocation-free rule)
__device__ float g_qp  [B_ * LQ * H_];        // [row][h] : query proj + bq
__device__ float g_c2T [B_ * H_ * LK];        // [b][h][k]: 2*(context proj + bc)
__device__ float g_attn[B_ * LQ * LK];        // softmax weights
__device__ ull   g_WT2 [2][DQ / 2][H_];       // [m][d2][h] = pk(W[h][2d2], W[h][2d2+1])

// ---------- f32x2 helpers ----------
__device__ __forceinline__ ull pk(float a, float b) {
    ull r; asm("mov.b64 %0, {%1, %2};" : "=l"(r) : "f"(a), "f"(b)); return r;
}
__device__ __forceinline__ void upk(ull v, float& a, float& b) {
    asm("mov.b64 {%0, %1}, %2;" : "=f"(a), "=f"(b) : "l"(v));
}
__device__ __forceinline__ ull add2(ull a, ull b) {
    ull r; asm("add.rn.f32x2 %0, %1, %2;" : "=l"(r) : "l"(a), "l"(b)); return r;
}
__device__ __forceinline__ ull fma2(ull a, ull b, ull c) {
    ull r; asm("fma.rn.f32x2 %0, %1, %2, %3;" : "=l"(r) : "l"(a), "l"(b), "l"(c)); return r;
}
__device__ __forceinline__ __half2 tanh2(__half2 v) {
    uint32_t x = *reinterpret_cast<uint32_t*>(&v), y;
    asm("tanh.approx.f16x2 %0, %1;" : "=r"(y) : "r"(x));
    return *reinterpret_cast<__half2*>(&y);
}

// ---------------------------------------------------------------------------
// Kernel 0: pack-transpose W -> g_WT2[m][d2][h] (coalesced writes over h)
// ---------------------------------------------------------------------------
__global__ __launch_bounds__(256) void wt_kernel(
    const float* __restrict__ Wq, const float* __restrict__ Wc)
{
    const int m = blockIdx.y;
    const float* W = m ? Wc : Wq;
    const int idx = blockIdx.x * 256 + threadIdx.x;   // 0..16383
    const int d2 = idx >> 7, h = idx & 127;
    const float a = W[h * DQ + 2 * d2];
    const float b = W[h * DQ + 2 * d2 + 1];
    g_WT2[m][d2][h] = pk(a, b);
}

// ---------------------------------------------------------------------------
// Kernel 1: projections, FFMA2 over d-pairs, W loads lane-coalesced via WT2.
// grid 256: m = bx>>7, 16-row tile = bx&127. 256 threads: h = t&127, rg = t>>7.
// ---------------------------------------------------------------------------
__global__ __launch_bounds__(256) void proj_kernel(
    const float* __restrict__ query, const float* __restrict__ context,
    const float* __restrict__ bq, const float* __restrict__ bc)
{
    __shared__ float insh[16][256];                  // 16 KB input tile

    const int m    = blockIdx.x >> 7;                // 0=query, 1=context
    const int tile = blockIdx.x & 127;
    const float* in   = m ? context : query;
    const float* bias = m ? bc : bq;
    const int t  = threadIdx.x;
    const int r0 = tile * 16;

    {   // coalesced coop load 16x256
        const float4* src = (const float4*)(in + (size_t)r0 * 256);
        float4* dst = (float4*)insh;
        #pragma unroll
        for (int i = t; i < 16 * 64; i += 256) dst[i] = src[i];
    }
    __syncthreads();

    const int h  = t & 127;
    const int rg = t >> 7;                           // rows rg*8 .. rg*8+7
    const float bb = bias[h];
    ull acc[8];
    #pragma unroll
    for (int j = 0; j < 8; j++) acc[j] = pk(bb, 0.0f);

    const ull* wp = &g_WT2[m][0][h];                 // stride H_ per d2
    #pragma unroll 4
    for (int d4 = 0; d4 < 64; d4++) {
        const ull w01 = wp[(2 * d4)     * H_];       // coalesced LDG.64 over h
        const ull w23 = wp[(2 * d4 + 1) * H_];
        #pragma unroll
        for (int j = 0; j < 8; j++) {
            const ulonglong2 q2 = *(const ulonglong2*)&insh[rg * 8 + j][d4 * 4]; // broadcast LDS.128
            acc[j] = fma2(w01, q2.x, acc[j]);
            acc[j] = fma2(w23, q2.y, acc[j]);
        }
    }

    #pragma unroll
    for (int j = 0; j < 8; j++) {
        float lo, hi; upk(acc[j], lo, hi);
        const float s = lo + hi;
        const int row = r0 + rg * 8 + j;
        if (m == 0) {
            g_qp[(size_t)row * H_ + h] = s;          // coalesced over h
        } else {
            const int b = row >> 9, k = row & 511;
            g_c2T[((size_t)b * H_ + h) * LK + k] = 2.0f * s;
        }
    }
}

// ---------------------------------------------------------------------------
// Kernel 2: scores + softmax. CTA = (b, 8 q), 256 CTAs, 256 threads.
// Thread: kt = t&127 -> k = 4*kt..4*kt+3 (one float4 of c2T), 4 q's (t>>7).
// tanh via MUFU f16x2 (2 tanh/issue). Accumulate f32x2 per k-pair.
// Fused softmax: warp w -> q0+w. bv dropped (softmax-invariant).
// ---------------------------------------------------------------------------
__global__ __launch_bounds__(256) void scores_kernel(const float* __restrict__ Wv)
{
    __shared__ ull  qsh2[8][H_];      // (qp, qp) per (q, h)   : 8 KB
    __shared__ ull  wv2[H_];          // (Wv, Wv)              : 1 KB
    __shared__ float sc[8][LK];       // scores                : 16 KB

    const int tile = blockIdx.x;          // 0..255
    const int b  = tile >> 6;             // 64 tiles per batch
    const int q0 = (tile & 63) * 8;
    const int t  = threadIdx.x;

    #pragma unroll
    for (int i = t; i < 8 * H_; i += 256) {
        const int q = i >> 7, h = i & 127;
        const float v = g_qp[((size_t)(b * LQ + q0 + q)) * H_ + h];
        qsh2[q][h] = pk(v, v);
    }
    if (t < H_) { const float w = Wv[t]; wv2[t] = pk(w, w); }
    __syncthreads();

    const int kt = t & 127;               // float4 chunk of k
    const int qg = (t >> 7) * 4;          // q-offset 0 or 4
    const ulonglong2* cp =
        (const ulonglong2*)(g_c2T + (size_t)b * H_ * LK) + kt;  // stride 128 per h

    ull acc[4][2];
    #pragma unroll
    for (int qi = 0; qi < 4; qi++) { acc[qi][0] = 0ULL; acc[qi][1] = 0ULL; }

    #pragma unroll 2
    for (int h = 0; h < H_; h++) {
        const ulonglong2 cc = cp[h * 128];     // LDG.128, coalesced over kt
        const ull wv = wv2[h];                 // broadcast
        #pragma unroll
        for (int qi = 0; qi < 4; qi++) {
            const ull qq = qsh2[qg + qi][h];   // broadcast
            const ull x01 = add2(qq, cc.x);
            const ull x23 = add2(qq, cc.y);
            float a0, a1, a2, a3;
            upk(x01, a0, a1); upk(x23, a2, a3);
            const float2 f01 = __half22float2(tanh2(__floats2half2_rn(a0, a1)));
            const float2 f23 = __half22float2(tanh2(__floats2half2_rn(a2, a3)));
            acc[qi][0] = fma2(pk(f01.x, f01.y), wv, acc[qi][0]);
            acc[qi][1] = fma2(pk(f23.x, f23.y), wv, acc[qi][1]);
        }
    }

    #pragma unroll
    for (int qi = 0; qi < 4; qi++) {
        float s0, s1, s2, s3;
        upk(acc[qi][0], s0, s1);
        upk(acc[qi][1], s2, s3);
        *(float4*)&sc[qg + qi][kt * 4] = make_float4(s0, s1, s2, s3);  // STS.128 cf
    }
    __syncthreads();

    // softmax: warp w handles q = q0 + w
    const int w = t >> 5, lane = t & 31;
    float e[16];
    float mx = -1e30f;
    #pragma unroll
    for (int j = 0; j < 16; j++) {
        e[j] = sc[w][lane + j * 32];
        mx = fmaxf(mx, e[j]);
    }
    #pragma unroll
    for (int off = 16; off > 0; off >>= 1)
        mx = fmaxf(mx, __shfl_xor_sync(0xffffffffu, mx, off));
    float s = 0.0f;
    #pragma unroll
    for (int j = 0; j < 16; j++) { e[j] = __expf(e[j] - mx); s += e[j]; }
    #pragma unroll
    for (int off = 16; off > 0; off >>= 1)
        s += __shfl_xor_sync(0xffffffffu, s, off);
    const float inv = 1.0f / s;
    float* dst = g_attn + ((size_t)b * LQ + q0 + w) * LK;
    #pragma unroll
    for (int j = 0; j < 16; j++) dst[lane + j * 32] = e[j] * inv;   // coalesced
}

// ---------------------------------------------------------------------------
// Kernel 3: out = attn @ context.  256 CTAs: (b, 16-q tile, D-half).
// thread: d4 = (t&31)+dh*32 (one float4 of D), qg = t>>5 (2 q each).
// ---------------------------------------------------------------------------
__global__ __launch_bounds__(256) void out_kernel(
    const float* __restrict__ context, float* __restrict__ out)
{
    __shared__ float attn_sh[16][LK];     // 32 KB

    const int bx = blockIdx.x;
    const int b  = bx >> 6;               // 64 tiles per batch
    const int q0 = ((bx >> 1) & 31) * 16;
    const int dh = bx & 1;
    const int t  = threadIdx.x;

    {
        const float4* src = (const float4*)(g_attn + ((size_t)b * LQ + q0) * LK);
        float4* dst = (float4*)attn_sh;
        #pragma unroll
        for (int i = t; i < 16 * 128; i += 256) dst[i] = src[i];
    }
    __syncthreads();

    const int d4 = (t & 31) + dh * 32;    // float4 index within Dc
    const int qg = t >> 5;                // 2 q's: q0+qg*2, +1
    const ulonglong2* ctx2 = (const ulonglong2*)(context + (size_t)b * LK * DC);

    ull acc[2][2];
    acc[0][0] = acc[0][1] = acc[1][0] = acc[1][1] = 0ULL;

    #pragma unroll 2
    for (int k = 0; k < LK; k++) {
        const ulonglong2 cc = ctx2[k * 64 + d4];      // LDG.128 coalesced
        #pragma unroll
        for (int qi = 0; qi < 2; qi++) {
            const float a = attn_sh[qg * 2 + qi][k];  // broadcast
            const ull aa = pk(a, a);
            acc[qi][0] = fma2(aa, cc.x, acc[qi][0]);
            acc[qi][1] = fma2(aa, cc.y, acc[qi][1]);
        }
    }

    #pragma unroll
    for (int qi = 0; qi < 2; qi++) {
        float x0, x1, x2, x3;
        upk(acc[qi][0], x0, x1);
        upk(acc[qi][1], x2, x3);
        float4* o = (float4*)(out + ((size_t)b * LQ + q0 + qg * 2 + qi) * DC + d4 * 4);
        *o = make_float4(x0, x1, x2, x3);
    }
}

// ---------------------------------------------------------------------------
extern "C" void kernel_launch(void* const* d_in, const int* in_sizes, int n_in,
                              void* d_out, int out_size)
{
    const float* query   = (const float*)d_in[0];
    const float* context = (const float*)d_in[1];
    const float* Wq      = (const float*)d_in[2];
    const float* bq      = (const float*)d_in[3];
    const float* Wc      = (const float*)d_in[4];
    const float* bc      = (const float*)d_in[5];
    const float* Wv      = (const float*)d_in[6];
    // d_in[7] = bv : constant pre-softmax shift, mathematically a no-op.

    wt_kernel    <<<dim3(64, 2), 256>>>(Wq, Wc);
    proj_kernel  <<<256, 256>>>(query, context, bq, bc);
    scores_kernel<<<256, 256>>>(Wv);
    out_kernel   <<<256, 256>>>(context, (float*)d_out);
}

// round 3
// speedup vs baseline: 1.3917x; 1.3917x over previous
#include <cuda_runtime.h>
#include <cuda_fp16.h>
#include <cstdint>

#define B_  4
#define LQ  512
#define LK  512
#define DQ  256
#define DC  256
#define H_  128

typedef unsigned long long ull;

// Scratch (__device__ globals: allocation-free rule)
__device__ float g_qp  [B_ * LQ * H_];        // [row][h] : query proj + bq
__device__ float g_c2T [B_ * H_ * LK];        // [b][h][k]: 2*(context proj + bc)
__device__ float g_attn[B_ * LQ * LK];        // softmax weights
__device__ ull   g_WT2 [2][DQ / 2][H_];       // [m][d2][h] = pk(W[h][2d2], W[h][2d2+1])

// ---------- f32x2 helpers ----------
__device__ __forceinline__ ull pk(float a, float b) {
    ull r; asm("mov.b64 %0, {%1, %2};" : "=l"(r) : "f"(a), "f"(b)); return r;
}
__device__ __forceinline__ void upk(ull v, float& a, float& b) {
    asm("mov.b64 {%0, %1}, %2;" : "=f"(a), "=f"(b) : "l"(v));
}
__device__ __forceinline__ ull add2(ull a, ull b) {
    ull r; asm("add.rn.f32x2 %0, %1, %2;" : "=l"(r) : "l"(a), "l"(b)); return r;
}
__device__ __forceinline__ ull fma2(ull a, ull b, ull c) {
    ull r; asm("fma.rn.f32x2 %0, %1, %2, %3;" : "=l"(r) : "l"(a), "l"(b), "l"(c)); return r;
}
__device__ __forceinline__ __half2 tanh2(__half2 v) {
    uint32_t x = *reinterpret_cast<uint32_t*>(&v), y;
    asm("tanh.approx.f16x2 %0, %1;" : "=r"(y) : "r"(x));
    return *reinterpret_cast<__half2*>(&y);
}

// ---------------------------------------------------------------------------
// Kernel 0: pack-transpose W -> g_WT2[m][d2][h] (coalesced writes over h)
// ---------------------------------------------------------------------------
__global__ __launch_bounds__(256) void wt_kernel(
    const float* __restrict__ Wq, const float* __restrict__ Wc)
{
    const int m = blockIdx.y;
    const float* W = m ? Wc : Wq;
    const int idx = blockIdx.x * 256 + threadIdx.x;   // 0..16383
    const int d2 = idx >> 7, h = idx & 127;
    const float a = W[h * DQ + 2 * d2];
    const float b = W[h * DQ + 2 * d2 + 1];
    g_WT2[m][d2][h] = pk(a, b);
}

// ---------------------------------------------------------------------------
// Kernel 1: projections, FFMA2 over d-pairs, W loads lane-coalesced via WT2.
// ---------------------------------------------------------------------------
__global__ __launch_bounds__(256) void proj_kernel(
    const float* __restrict__ query, const float* __restrict__ context,
    const float* __restrict__ bq, const float* __restrict__ bc)
{
    __shared__ float insh[16][256];                  // 16 KB input tile

    const int m    = blockIdx.x >> 7;                // 0=query, 1=context
    const int tile = blockIdx.x & 127;
    const float* in   = m ? context : query;
    const float* bias = m ? bc : bq;
    const int t  = threadIdx.x;
    const int r0 = tile * 16;

    {   // coalesced coop load 16x256
        const float4* src = (const float4*)(in + (size_t)r0 * 256);
        float4* dst = (float4*)insh;
        #pragma unroll
        for (int i = t; i < 16 * 64; i += 256) dst[i] = src[i];
    }
    __syncthreads();

    const int h  = t & 127;
    const int rg = t >> 7;                           // rows rg*8 .. rg*8+7
    const float bb = bias[h];
    ull acc[8];
    #pragma unroll
    for (int j = 0; j < 8; j++) acc[j] = pk(bb, 0.0f);

    const ull* wp = &g_WT2[m][0][h];                 // stride H_ per d2
    #pragma unroll 4
    for (int d4 = 0; d4 < 64; d4++) {
        const ull w01 = wp[(2 * d4)     * H_];       // coalesced LDG.64 over h
        const ull w23 = wp[(2 * d4 + 1) * H_];
        #pragma unroll
        for (int j = 0; j < 8; j++) {
            const ulonglong2 q2 = *(const ulonglong2*)&insh[rg * 8 + j][d4 * 4]; // broadcast LDS.128
            acc[j] = fma2(w01, q2.x, acc[j]);
            acc[j] = fma2(w23, q2.y, acc[j]);
        }
    }

    #pragma unroll
    for (int j = 0; j < 8; j++) {
        float lo, hi; upk(acc[j], lo, hi);
        const float s = lo + hi;
        const int row = r0 + rg * 8 + j;
        if (m == 0) {
            g_qp[(size_t)row * H_ + h] = s;          // coalesced over h
        } else {
            const int b = row >> 9, k = row & 511;
            g_c2T[((size_t)b * H_ + h) * LK + k] = 2.0f * s;
        }
    }
}

// ---------------------------------------------------------------------------
// Kernel 2: scores + softmax (MUFU f16x2-bound, near HW floor ~15us).
// ---------------------------------------------------------------------------
__global__ __launch_bounds__(256) void scores_kernel(const float* __restrict__ Wv)
{
    __shared__ ull  qsh2[8][H_];      // (qp, qp) per (q, h)   : 8 KB
    __shared__ ull  wv2[H_];          // (Wv, Wv)              : 1 KB
    __shared__ float sc[8][LK];       // scores                : 16 KB

    const int tile = blockIdx.x;          // 0..255
    const int b  = tile >> 6;             // 64 tiles per batch
    const int q0 = (tile & 63) * 8;
    const int t  = threadIdx.x;

    #pragma unroll
    for (int i = t; i < 8 * H_; i += 256) {
        const int q = i >> 7, h = i & 127;
        const float v = g_qp[((size_t)(b * LQ + q0 + q)) * H_ + h];
        qsh2[q][h] = pk(v, v);
    }
    if (t < H_) { const float w = Wv[t]; wv2[t] = pk(w, w); }
    __syncthreads();

    const int kt = t & 127;               // float4 chunk of k
    const int qg = (t >> 7) * 4;          // q-offset 0 or 4
    const ulonglong2* cp =
        (const ulonglong2*)(g_c2T + (size_t)b * H_ * LK) + kt;  // stride 128 per h

    ull acc[4][2];
    #pragma unroll
    for (int qi = 0; qi < 4; qi++) { acc[qi][0] = 0ULL; acc[qi][1] = 0ULL; }

    #pragma unroll 2
    for (int h = 0; h < H_; h++) {
        const ulonglong2 cc = cp[h * 128];     // LDG.128, coalesced over kt
        const ull wv = wv2[h];                 // broadcast
        #pragma unroll
        for (int qi = 0; qi < 4; qi++) {
            const ull qq = qsh2[qg + qi][h];   // broadcast
            const ull x01 = add2(qq, cc.x);
            const ull x23 = add2(qq, cc.y);
            float a0, a1, a2, a3;
            upk(x01, a0, a1); upk(x23, a2, a3);
            const float2 f01 = __half22float2(tanh2(__floats2half2_rn(a0, a1)));
            const float2 f23 = __half22float2(tanh2(__floats2half2_rn(a2, a3)));
            acc[qi][0] = fma2(pk(f01.x, f01.y), wv, acc[qi][0]);
            acc[qi][1] = fma2(pk(f23.x, f23.y), wv, acc[qi][1]);
        }
    }

    #pragma unroll
    for (int qi = 0; qi < 4; qi++) {
        float s0, s1, s2, s3;
        upk(acc[qi][0], s0, s1);
        upk(acc[qi][1], s2, s3);
        *(float4*)&sc[qg + qi][kt * 4] = make_float4(s0, s1, s2, s3);
    }
    __syncthreads();

    // softmax: warp w handles q = q0 + w
    const int w = t >> 5, lane = t & 31;
    float e[16];
    float mx = -1e30f;
    #pragma unroll
    for (int j = 0; j < 16; j++) {
        e[j] = sc[w][lane + j * 32];
        mx = fmaxf(mx, e[j]);
    }
    #pragma unroll
    for (int off = 16; off > 0; off >>= 1)
        mx = fmaxf(mx, __shfl_xor_sync(0xffffffffu, mx, off));
    float s = 0.0f;
    #pragma unroll
    for (int j = 0; j < 16; j++) { e[j] = __expf(e[j] - mx); s += e[j]; }
    #pragma unroll
    for (int off = 16; off > 0; off >>= 1)
        s += __shfl_xor_sync(0xffffffffu, s, off);
    const float inv = 1.0f / s;
    float* dst = g_attn + ((size_t)b * LQ + q0 + w) * LK;
    #pragma unroll
    for (int j = 0; j < 16; j++) dst[lane + j * 32] = e[j] * inv;   // coalesced
}

// ---------------------------------------------------------------------------
// Kernel 3: out = attn @ context  — smem-tiled GEMM, FFMA2 q-pair packing.
// BM=64 (q), BN=64 (d), BK=32 (k). 128 CTAs = 4b x 8qt x 4dt. 256 threads.
// Register-prefetch -> smem pipeline; thread computes 4q x 4d via 8 f32x2 accs.
// ---------------------------------------------------------------------------
__global__ __launch_bounds__(256) void out_kernel(
    const float* __restrict__ context, float* __restrict__ out)
{
    __shared__ float a_sh[32][68];    // [k][q] transposed attn tile (pad 68)
    __shared__ float c_sh[32][68];    // [k][d] ctx tile (pad 68)

    const int bx = blockIdx.x;        // 0..127
    const int b  = bx >> 5;
    const int q0 = ((bx >> 2) & 7) * 64;
    const int d0 = (bx & 3) * 64;
    const int t  = threadIdx.x;
    const int tx = t & 15;            // d-group: d0 + tx*4
    const int ty = t >> 4;            // q-group: q0 + ty*4

    // global load coords
    const int ar = t >> 3, ac4 = t & 7;     // attn: rows ar, ar+32; 8 float4/row
    const int cr = t >> 4, cc4 = t & 15;    // ctx:  rows cr, cr+16; 16 float4/row

    const float4* ag = (const float4*)(g_attn + ((size_t)b * LQ + q0) * LK); // row = 128 f4
    const float4* cg = (const float4*)(context + (size_t)b * LK * DC + d0);  // row = 64 f4

    // prefetch stage 0
    float4 pa0 = ag[(size_t)ar * 128 + ac4];
    float4 pa1 = ag[(size_t)(ar + 32) * 128 + ac4];
    float4 pc0 = cg[(size_t)cr * 64 + cc4];
    float4 pc1 = cg[(size_t)(cr + 16) * 64 + cc4];

    ull acc[2][4];
    #pragma unroll
    for (int p = 0; p < 2; p++)
        #pragma unroll
        for (int d = 0; d < 4; d++) acc[p][d] = 0ULL;

    #pragma unroll 1
    for (int s = 0; s < 16; s++) {
        __syncthreads();
        // attn tile -> smem transposed [k][q]
        a_sh[ac4 * 4 + 0][ar] = pa0.x;
        a_sh[ac4 * 4 + 1][ar] = pa0.y;
        a_sh[ac4 * 4 + 2][ar] = pa0.z;
        a_sh[ac4 * 4 + 3][ar] = pa0.w;
        a_sh[ac4 * 4 + 0][ar + 32] = pa1.x;
        a_sh[ac4 * 4 + 1][ar + 32] = pa1.y;
        a_sh[ac4 * 4 + 2][ar + 32] = pa1.z;
        a_sh[ac4 * 4 + 3][ar + 32] = pa1.w;
        // ctx tile -> smem direct [k][d]
        *(float4*)&c_sh[cr][cc4 * 4]      = pc0;
        *(float4*)&c_sh[cr + 16][cc4 * 4] = pc1;
        __syncthreads();

        if (s < 15) {   // prefetch next stage (overlaps compute below)
            const int k4 = (s + 1) * 8;            // float4 offset in k
            const int kr = (s + 1) * 32;           // row offset in k
            pa0 = ag[(size_t)ar * 128 + k4 + ac4];
            pa1 = ag[(size_t)(ar + 32) * 128 + k4 + ac4];
            pc0 = cg[(size_t)(kr + cr) * 64 + cc4];
            pc1 = cg[(size_t)(kr + cr + 16) * 64 + cc4];
        }

        #pragma unroll
        for (int k = 0; k < 32; k++) {
            const ulonglong2 a2 = *(const ulonglong2*)&a_sh[k][ty * 4]; // (q0,q1),(q2,q3)
            const float4 c4 = *(const float4*)&c_sh[k][tx * 4];
            const ull cx = pk(c4.x, c4.x);
            const ull cy = pk(c4.y, c4.y);
            const ull cz = pk(c4.z, c4.z);
            const ull cw = pk(c4.w, c4.w);
            acc[0][0] = fma2(a2.x, cx, acc[0][0]);
            acc[0][1] = fma2(a2.x, cy, acc[0][1]);
            acc[0][2] = fma2(a2.x, cz, acc[0][2]);
            acc[0][3] = fma2(a2.x, cw, acc[0][3]);
            acc[1][0] = fma2(a2.y, cx, acc[1][0]);
            acc[1][1] = fma2(a2.y, cy, acc[1][1]);
            acc[1][2] = fma2(a2.y, cz, acc[1][2]);
            acc[1][3] = fma2(a2.y, cw, acc[1][3]);
        }
    }

    // unpack: acc[p][d] = (out[q=ty*4+2p], out[q=ty*4+2p+1]) at d = tx*4+d
    float o[4][4];
    #pragma unroll
    for (int p = 0; p < 2; p++)
        #pragma unroll
        for (int d = 0; d < 4; d++)
            upk(acc[p][d], o[2 * p][d], o[2 * p + 1][d]);

    #pragma unroll
    for (int qi = 0; qi < 4; qi++) {
        float4* dst = (float4*)(out + ((size_t)b * LQ + q0 + ty * 4 + qi) * DC
                                + d0 + tx * 4);
        *dst = make_float4(o[qi][0], o[qi][1], o[qi][2], o[qi][3]);
    }
}

// ---------------------------------------------------------------------------
extern "C" void kernel_launch(void* const* d_in, const int* in_sizes, int n_in,
                              void* d_out, int out_size)
{
    const float* query   = (const float*)d_in[0];
    const float* context = (const float*)d_in[1];
    const float* Wq      = (const float*)d_in[2];
    const float* bq      = (const float*)d_in[3];
    const float* Wc      = (const float*)d_in[4];
    const float* bc      = (const float*)d_in[5];
    const float* Wv      = (const float*)d_in[6];
    // d_in[7] = bv : constant pre-softmax shift, mathematically a no-op.

    wt_kernel    <<<dim3(64, 2), 256>>>(Wq, Wc);
    proj_kernel  <<<256, 256>>>(query, context, bq, bc);
    scores_kernel<<<256, 256>>>(Wv);
    out_kernel   <<<128, 256>>>(context, (float*)d_out);
}